// round 4
// baseline (speedup 1.0000x reference)
#include <cuda_runtime.h>
#include <math.h>
#include <stdint.h>

// Problem constants
#define Bb 32
#define Tt 64
#define Ee 64
#define Uu 32
#define D0 300
#define D1 100
#define Ss 9
#define CELL 64
#define Cc 6
#define ROWS (Bb*Tt)      // 2048
#define G4E (4*Ee)        // 256

// Device scratch
__device__ float g_xproj0[ROWS * G4E];
__device__ float g_xproj1[ROWS * G4E];
__device__ float g_h0[ROWS * Ee];
__device__ float g_h1[ROWS * Ee];
__device__ float g_krT[Ee * Uu];   // [e][u]
__device__ float g_kiT[Ee * Uu];

// ---------------------------------------------------------------------------
// fast activations (MUFU-based, clamped)
// ---------------------------------------------------------------------------
__device__ __forceinline__ float fsig(float x) {
    x = fminf(fmaxf(x, -30.f), 30.f);
    return __fdividef(1.f, 1.f + __expf(-x));
}
__device__ __forceinline__ float ftanh_(float x) {
    x = fminf(fmaxf(x, -15.f), 15.f);
    float e = __expf(2.f * x);
    return 1.f - __fdividef(2.f, e + 1.f);
}

// packed f32x2 helpers (Blackwell)
__device__ __forceinline__ unsigned long long ffma2(unsigned long long a,
                                                    unsigned long long b,
                                                    unsigned long long c) {
    unsigned long long d;
    asm("fma.rn.f32x2 %0, %1, %2, %3;" : "=l"(d) : "l"(a), "l"(b), "l"(c));
    return d;
}
__device__ __forceinline__ unsigned long long fadd2(unsigned long long a,
                                                    unsigned long long b) {
    unsigned long long d;
    asm("add.rn.f32x2 %0, %1, %2;" : "=l"(d) : "l"(a), "l"(b));
    return d;
}

// ---------------------------------------------------------------------------
// Kernel 1: merged input-projection GEMM (both modalities) + prep slice.
// grid = (5, 32, 2): x in [0,4) -> 64-wide N tiles; x==4,y==0,z==0 -> prep.
// Tiles: BM=64, BN=64, BK=16. 128 threads, 4m x 8n microtile (32 acc regs).
// Double-buffered smem, register prefetch, one barrier per K-tile.
// Per warp-kk: 3x LDS.128 (1.5 B/MAC) + 32 FFMA -> FMA-pipe-bound config.
// out[m][n] = umask[m]*sum_k A[m][k]*W[n][k] + bih[n] + bhh[n]
// ---------------------------------------------------------------------------
#define BKK 16
__global__ void __launch_bounds__(128) gemm_xproj(
    const float* __restrict__ x0, const float* __restrict__ Wih0,
    const float* __restrict__ bih0, const float* __restrict__ bhh0,
    const float* __restrict__ x1, const float* __restrict__ Wih1,
    const float* __restrict__ bih1, const float* __restrict__ bhh1,
    const float* __restrict__ umask, const float* __restrict__ mk) {

    if (blockIdx.x == 4) {
        if (blockIdx.y != 0 || blockIdx.z != 0) return;
        // prep: normalize measurement kernel, store transposed
        __shared__ float inv_norm[Uu];
        int tid = threadIdx.x;
        if (tid < Uu) {
            float s = 0.f;
            const float* p = mk + tid * (Ee * 2);
            #pragma unroll 8
            for (int i = 0; i < Ee * 2; i++) s += p[i] * p[i];
            inv_norm[tid] = 1.f / fmaxf(sqrtf(s), 1e-12f);
        }
        __syncthreads();
        for (int idx = tid; idx < Uu * Ee; idx += blockDim.x) {
            int u = idx >> 6;
            int e = idx & 63;
            float inv = inv_norm[u];
            g_krT[e * Uu + u] = mk[(u * Ee + e) * 2 + 0] * inv;
            g_kiT[e * Uu + u] = mk[(u * Ee + e) * 2 + 1] * inv;
        }
        return;
    }

    int mod = blockIdx.z;
    const float* A   = mod ? x1 : x0;
    const float* W   = mod ? Wih1 : Wih0;
    const float* bih = mod ? bih1 : bih0;
    const float* bhh = mod ? bhh1 : bhh0;
    float* out = mod ? g_xproj1 : g_xproj0;
    const int K = mod ? D1 : D0;

    __shared__ __align__(16) float As[2][BKK][68];   // [buf][k][m], pad 4
    __shared__ __align__(16) float Ws[2][BKK][68];   // [buf][k][n], pad 4

    int tid = threadIdx.x;
    int lk = tid & 15;          // k within tile
    int lm = tid >> 4;          // 0..7
    int bm = blockIdx.y * 64, bn = blockIdx.x * 64;

    const float* Abase = A + (size_t)(bm + lm) * K;
    const float* Wbase = W + (size_t)(bn + lm) * K;
    const size_t rstride = (size_t)8 * K;

    const int ntiles = (K + 15) >> 4;

    float av[8], wv[8];
    // prologue: tile 0 (k = lk < 16 < K)
    #pragma unroll
    for (int j = 0; j < 8; j++) {
        av[j] = Abase[j * rstride + lk];
        wv[j] = Wbase[j * rstride + lk];
    }
    #pragma unroll
    for (int j = 0; j < 8; j++) {
        As[0][lk][lm + 8 * j] = av[j];
        Ws[0][lk][lm + 8 * j] = wv[j];
    }
    __syncthreads();

    float acc[4][8];
    #pragma unroll
    for (int i = 0; i < 4; i++)
        #pragma unroll
        for (int j = 0; j < 8; j++) acc[i][j] = 0.f;

    int tx = tid & 7;           // n-octet: columns tx*8 .. tx*8+7
    int ty = tid >> 3;          // m-quad:  rows    ty*4 .. ty*4+3

    for (int tl = 0; tl < ntiles; tl++) {
        int cur = tl & 1;
        bool has = (tl + 1) < ntiles;
        if (has) {
            int k = (tl + 1) * BKK + lk;
            bool v = k < K;
            #pragma unroll
            for (int j = 0; j < 8; j++) {
                av[j] = v ? Abase[j * rstride + k] : 0.f;
                wv[j] = v ? Wbase[j * rstride + k] : 0.f;
            }
        }
        #pragma unroll
        for (int kk = 0; kk < BKK; kk++) {
            float4 a4 = *(const float4*)&As[cur][kk][ty * 4];
            float4 w0 = *(const float4*)&Ws[cur][kk][tx * 8];
            float4 w1 = *(const float4*)&Ws[cur][kk][tx * 8 + 4];
            float a[4] = {a4.x, a4.y, a4.z, a4.w};
            float w[8] = {w0.x, w0.y, w0.z, w0.w, w1.x, w1.y, w1.z, w1.w};
            #pragma unroll
            for (int i = 0; i < 4; i++)
                #pragma unroll
                for (int j = 0; j < 8; j++)
                    acc[i][j] += a[i] * w[j];
        }
        if (has) {
            int nb = cur ^ 1;
            #pragma unroll
            for (int j = 0; j < 8; j++) {
                As[nb][lk][lm + 8 * j] = av[j];
                Ws[nb][lk][lm + 8 * j] = wv[j];
            }
        }
        __syncthreads();
    }

    int n = bn + tx * 8;
    float bv[8];
    #pragma unroll
    for (int j = 0; j < 8; j++) bv[j] = bih[n + j] + bhh[n + j];
    #pragma unroll
    for (int i = 0; i < 4; i++) {
        int m = bm + ty * 4 + i;
        float um = umask[m];
        float4 o0, o1;
        o0.x = um * acc[i][0] + bv[0];
        o0.y = um * acc[i][1] + bv[1];
        o0.z = um * acc[i][2] + bv[2];
        o0.w = um * acc[i][3] + bv[3];
        o1.x = um * acc[i][4] + bv[4];
        o1.y = um * acc[i][5] + bv[5];
        o1.z = um * acc[i][6] + bv[6];
        o1.w = um * acc[i][7] + bv[7];
        *(float4*)&out[(size_t)m * G4E + n] = o0;
        *(float4*)&out[(size_t)m * G4E + n + 4] = o1;
    }
}

// ---------------------------------------------------------------------------
// Kernel 2: LSTM recurrence (shuffle gather, double-buffered h, one barrier
// per step, prefetched xp, packed f32x2 dot).
// ---------------------------------------------------------------------------
__global__ void __launch_bounds__(256, 1) lstm_kernel(
    const float* __restrict__ Whh0, const float* __restrict__ Whh1) {
    int mod = blockIdx.x >> 5;
    int b = blockIdx.x & 31;
    const float* Whh = mod ? Whh1 : Whh0;
    const float* xp = (mod ? g_xproj1 : g_xproj0) + (size_t)b * Tt * G4E;
    float* hout = (mod ? g_h1 : g_h0) + (size_t)b * Tt * Ee;

    int tid = threadIdx.x;
    int w = tid >> 5, l = tid & 31;
    int gt = l & 3;
    int cell = w * 8 + (l >> 2);
    int r = gt * 64 + cell;

    unsigned long long wp[32];
    {
        const float2* src = (const float2*)(Whh + (size_t)r * Ee);
        #pragma unroll
        for (int i = 0; i < 32; i++) {
            union { float2 f; unsigned long long u; } cv;
            cv.f = src[i];
            wp[i] = cv.u;
        }
    }

    __shared__ __align__(16) float hs[2][Ee];
    if (tid < Ee) hs[0][tid] = 0.f;
    float c = 0.f;
    __syncthreads();

    float gpre = xp[r];
    #pragma unroll 1
    for (int t = 0; t < Tt; t++) {
        float gnext = (t + 1 < Tt) ? xp[(t + 1) * G4E + r] : 0.f;

        const ulonglong2* h2 = (const ulonglong2*)hs[t & 1];
        unsigned long long a0 = 0ull, a1 = 0ull, a2 = 0ull, a3 = 0ull;
        #pragma unroll
        for (int i = 0; i < 16; i += 2) {
            ulonglong2 hv = h2[i];
            a0 = ffma2(wp[2 * i + 0], hv.x, a0);
            a1 = ffma2(wp[2 * i + 1], hv.y, a1);
            ulonglong2 hv2 = h2[i + 1];
            a2 = ffma2(wp[2 * i + 2], hv2.x, a2);
            a3 = ffma2(wp[2 * i + 3], hv2.y, a3);
        }
        unsigned long long s = fadd2(fadd2(a0, a1), fadd2(a2, a3));
        float lo, hi;
        asm("mov.b64 {%0,%1}, %2;" : "=f"(lo), "=f"(hi) : "l"(s));
        float g = gpre + lo + hi;
        gpre = gnext;

        float act = (gt == 2) ? ftanh_(g) : fsig(g);

        float v1 = __shfl_xor_sync(0xffffffffu, act, 1);
        float v2 = __shfl_xor_sync(0xffffffffu, act, 2);
        float v3 = __shfl_xor_sync(0xffffffffu, v1, 2);

        if (gt == 0) {
            c = v1 * c + act * v2;
            float h = ftanh_(v3 * ftanh_(c));
            hs[(t + 1) & 1][cell] = h;
            hout[t * Ee + cell] = h;
        }
        __syncthreads();
    }
}

// ---------------------------------------------------------------------------
// Kernel 3: normalize + phase + measurement + MLP + log_softmax.
// 256 blocks, 8 rows each (2 groups of 4) — weight staging amortized 2x.
// ---------------------------------------------------------------------------
__global__ void __launch_bounds__(256) epilogue_kernel(
    const float* __restrict__ smask, const float* __restrict__ phase_table,
    const float* __restrict__ W1, const float* __restrict__ b1,
    const float* __restrict__ W2, const float* __restrict__ b2,
    float* __restrict__ out) {
    __shared__ float krT[Ee * Uu];
    __shared__ float kiT[Ee * Uu];
    __shared__ float W1s[CELL * 65];
    __shared__ float r0s[4][Ee], i0s[4][Ee], r1s[4][Ee], i1s[4][Ee];
    __shared__ float ms[4][2 * Uu];
    __shared__ float hids[4][CELL];
    __shared__ float preds[4][8];
    __shared__ float part[4][2][2];
    __shared__ int sidx[4];
    __shared__ float lse_s[4];

    int tid = threadIdx.x;
    int slot = tid >> 6;
    int lt = tid & 63;

    for (int i = tid; i < Ee * Uu; i += 256) { krT[i] = g_krT[i]; kiT[i] = g_kiT[i]; }
    for (int i = tid; i < CELL * CELL; i += 256) {
        int cc = i >> 6, k = i & 63;
        W1s[cc * 65 + k] = W1[i];
    }

    for (int grp = 0; grp < 2; grp++) {
        int row = blockIdx.x * 8 + grp * 4 + slot;

        float h0 = g_h0[row * Ee + lt];
        float h1 = g_h1[row * Ee + lt];
        float v0 = h0 * h0, v1 = h1 * h1;
        #pragma unroll
        for (int off = 16; off; off >>= 1) {
            v0 += __shfl_xor_sync(0xffffffffu, v0, off);
            v1 += __shfl_xor_sync(0xffffffffu, v1, off);
        }
        if ((tid & 31) == 0) { part[slot][lt >> 5][0] = v0; part[slot][lt >> 5][1] = v1; }
        if (lt == 0) {
            const float* sm = smask + row * Ss;
            float best = sm[0]; int bi = 0;
            #pragma unroll
            for (int e = 1; e < Ss; e++) { float v = sm[e]; if (v > best) { best = v; bi = e; } }
            sidx[slot] = bi;
        }
        __syncthreads();

        float s0 = part[slot][0][0] + part[slot][1][0];
        float s1 = part[slot][0][1] + part[slot][1][1];
        float inv0 = 1.f / fmaxf(sqrtf(s0), 1e-12f);
        float inv1 = 1.f / fmaxf(sqrtf(s1), 1e-12f);
        float n0 = h0 * inv0, n1 = h1 * inv1;

        float ph = phase_table[sidx[slot] * Ee + lt];
        float cp = cosf(ph), sp = sinf(ph);
        r0s[slot][lt] = cp * n0; i0s[slot][lt] = sp * n0;
        r1s[slot][lt] = cp * n1; i1s[slot][lt] = sp * n1;
        __syncthreads();

        {
            int mo = lt >> 5;
            int uu = lt & 31;
            const float* R = mo ? r1s[slot] : r0s[slot];
            const float* I = mo ? i1s[slot] : i0s[slot];
            float pr = 0.f, pi = 0.f;
            #pragma unroll 16
            for (int e = 0; e < Ee; e++) {
                float kr = krT[e * Uu + uu];
                float ki = kiT[e * Uu + uu];
                float rr = R[e], im = I[e];
                pr += kr * rr - ki * im;
                pi += ki * rr + kr * im;
            }
            ms[slot][lt] = pr * pr + pi * pi;
        }
        __syncthreads();

        {
            int cc = lt;
            float acc = b1[cc];
            #pragma unroll 16
            for (int k = 0; k < CELL; k++) acc += ms[slot][k] * W1s[cc * 65 + k];
            hids[slot][cc] = fmaxf(acc, 0.f);
        }
        __syncthreads();

        if (lt < Cc) {
            float acc = b2[lt];
            const float* w2 = W2 + lt * CELL;
            #pragma unroll 16
            for (int k = 0; k < CELL; k++) acc += hids[slot][k] * w2[k];
            preds[slot][lt] = tanhf(acc);
        }
        __syncthreads();

        if (lt == 0) {
            float m = preds[slot][0];
            #pragma unroll
            for (int k = 1; k < Cc; k++) m = fmaxf(m, preds[slot][k]);
            float se = 0.f;
            #pragma unroll
            for (int k = 0; k < Cc; k++) se += expf(preds[slot][k] - m);
            lse_s[slot] = m + logf(se);
        }
        __syncthreads();

        if (lt < Cc) out[row * Cc + lt] = preds[slot][lt] - lse_s[slot];
        __syncthreads();
    }
}

// ---------------------------------------------------------------------------
extern "C" void kernel_launch(void* const* d_in, const int* in_sizes, int n_in,
                              void* d_out, int out_size) {
    const float* x0        = (const float*)d_in[0];
    const float* x1        = (const float*)d_in[1];
    const float* smask     = (const float*)d_in[2];
    const float* umask     = (const float*)d_in[3];
    const float* W_ih0     = (const float*)d_in[4];
    const float* W_hh0     = (const float*)d_in[5];
    const float* b_ih0     = (const float*)d_in[6];
    const float* b_hh0     = (const float*)d_in[7];
    const float* W_ih1     = (const float*)d_in[8];
    const float* W_hh1     = (const float*)d_in[9];
    const float* b_ih1     = (const float*)d_in[10];
    const float* b_hh1     = (const float*)d_in[11];
    const float* phase_tab = (const float*)d_in[12];
    const float* meas_k    = (const float*)d_in[13];
    const float* W1        = (const float*)d_in[14];
    const float* b1        = (const float*)d_in[15];
    const float* W2        = (const float*)d_in[16];
    const float* b2        = (const float*)d_in[17];
    float* out = (float*)d_out;

    dim3 ggrid(5, ROWS / 64, 2);   // (5, 32, 2)
    gemm_xproj<<<ggrid, 128>>>(x0, W_ih0, b_ih0, b_hh0,
                               x1, W_ih1, b_ih1, b_hh1, umask, meas_k);

    lstm_kernel<<<64, 256>>>(W_hh0, W_hh1);

    epilogue_kernel<<<ROWS / 8, 256>>>(smask, phase_tab, W1, b1, W2, b2, out);
}

// round 5
// speedup vs baseline: 1.1581x; 1.1581x over previous
#include <cuda_runtime.h>
#include <math.h>
#include <stdint.h>

// Problem constants
#define Bb 32
#define Tt 64
#define Ee 64
#define Uu 32
#define D0 300
#define D1 100
#define Ss 9
#define CELL 64
#define Cc 6
#define ROWS (Bb*Tt)      // 2048
#define G4E (4*Ee)        // 256
#define KC 100            // uniform K-chunk

// Device scratch: mod0 xproj split into 3 K-chunk partials
__device__ float g_xp0a[ROWS * G4E];
__device__ float g_xp0b[ROWS * G4E];
__device__ float g_xp0c[ROWS * G4E];
__device__ float g_xp1 [ROWS * G4E];
__device__ float g_h0[ROWS * Ee];
__device__ float g_h1[ROWS * Ee];
__device__ float g_krT[Ee * Uu];   // [e][u]
__device__ float g_kiT[Ee * Uu];

// ---------------------------------------------------------------------------
// fast activations: single-instruction MUFU.TANH
// ---------------------------------------------------------------------------
__device__ __forceinline__ float tanha(float x) {
    float y;
    asm("tanh.approx.f32 %0, %1;" : "=f"(y) : "f"(x));
    return y;
}
__device__ __forceinline__ float fsig(float x) {
    return fmaf(tanha(0.5f * x), 0.5f, 0.5f);
}

// packed f32x2 helpers (Blackwell)
__device__ __forceinline__ unsigned long long ffma2(unsigned long long a,
                                                    unsigned long long b,
                                                    unsigned long long c) {
    unsigned long long d;
    asm("fma.rn.f32x2 %0, %1, %2, %3;" : "=l"(d) : "l"(a), "l"(b), "l"(c));
    return d;
}
__device__ __forceinline__ unsigned long long fadd2(unsigned long long a,
                                                    unsigned long long b) {
    unsigned long long d;
    asm("add.rn.f32x2 %0, %1, %2;" : "=l"(d) : "l"(a), "l"(b));
    return d;
}

// ---------------------------------------------------------------------------
// Kernel 1: input-projection GEMM, uniform K=100 chunks + prep slice.
// grid = (5, 64, 4): x in [0,4) -> 64-wide N tiles; x==4,y==0,z==0 -> prep.
// z = 0,1,2 -> mod0 K-chunk z (k offset z*100); z = 3 -> mod1.
// Tiles: BM=32, BN=64, BK=16. 256 threads, 2x4 microtile. Double-buffered,
// one barrier per K-tile. Bias added only by z==0 and z==3.
// ---------------------------------------------------------------------------
#define BKK 16
__global__ void __launch_bounds__(256) gemm_xproj(
    const float* __restrict__ x0, const float* __restrict__ Wih0,
    const float* __restrict__ bih0, const float* __restrict__ bhh0,
    const float* __restrict__ x1, const float* __restrict__ Wih1,
    const float* __restrict__ bih1, const float* __restrict__ bhh1,
    const float* __restrict__ umask, const float* __restrict__ mk) {

    if (blockIdx.x == 4) {
        if (blockIdx.y != 0 || blockIdx.z != 0) return;
        // prep: normalize measurement kernel, store transposed
        __shared__ float inv_norm[Uu];
        int tid = threadIdx.x;
        if (tid < Uu) {
            float s = 0.f;
            const float* p = mk + tid * (Ee * 2);
            #pragma unroll 8
            for (int i = 0; i < Ee * 2; i++) s += p[i] * p[i];
            inv_norm[tid] = 1.f / fmaxf(sqrtf(s), 1e-12f);
        }
        __syncthreads();
        for (int idx = tid; idx < Uu * Ee; idx += blockDim.x) {
            int u = idx >> 6;
            int e = idx & 63;
            float inv = inv_norm[u];
            g_krT[e * Uu + u] = mk[(u * Ee + e) * 2 + 0] * inv;
            g_kiT[e * Uu + u] = mk[(u * Ee + e) * 2 + 1] * inv;
        }
        return;
    }

    int z = blockIdx.z;
    bool mod1 = (z == 3);
    const float* A   = mod1 ? x1 : x0;
    const float* W   = mod1 ? Wih1 : Wih0;
    const float* bih = mod1 ? bih1 : bih0;
    const float* bhh = mod1 ? bhh1 : bhh0;
    float* out = (z == 0) ? g_xp0a : (z == 1) ? g_xp0b : (z == 2) ? g_xp0c : g_xp1;
    const int Ks = mod1 ? D1 : D0;      // row stride
    const int k0 = mod1 ? 0 : z * KC;   // chunk offset
    const bool addb = (z == 0) || mod1;

    __shared__ __align__(16) float As[2][BKK][34];   // [buf][k][m], pad 2
    __shared__ __align__(16) float Ws[2][BKK][68];   // [buf][k][n], pad 4

    int tid = threadIdx.x;
    int lk = tid & 15;          // k within tile
    int lm = tid >> 4;          // 0..15
    int bm = blockIdx.y * 32, bn = blockIdx.x * 64;

    const float* Ar0 = A + (size_t)(bm + lm) * Ks + k0;
    const float* Ar1 = Ar0 + (size_t)16 * Ks;
    const float* Wr0 = W + (size_t)(bn + lm) * Ks + k0;
    const float* Wr1 = Wr0 + (size_t)16 * Ks;
    const float* Wr2 = Wr0 + (size_t)32 * Ks;
    const float* Wr3 = Wr0 + (size_t)48 * Ks;

    const int ntiles = (KC + BKK - 1) / BKK;   // 7

    float a0 = Ar0[lk], a1 = Ar1[lk];
    float w0 = Wr0[lk], w1 = Wr1[lk], w2 = Wr2[lk], w3 = Wr3[lk];
    As[0][lk][lm] = a0;  As[0][lk][lm + 16] = a1;
    Ws[0][lk][lm] = w0;  Ws[0][lk][lm + 16] = w1;
    Ws[0][lk][lm + 32] = w2;  Ws[0][lk][lm + 48] = w3;
    __syncthreads();

    float acc[2][4] = {};
    int tx = tid & 15;          // n-quad
    int ty = tid >> 4;          // m-pair

    for (int tl = 0; tl < ntiles; tl++) {
        int cur = tl & 1;
        bool has = (tl + 1) < ntiles;
        if (has) {
            int k = (tl + 1) * BKK + lk;
            bool v = k < KC;
            a0 = v ? Ar0[k] : 0.f;  a1 = v ? Ar1[k] : 0.f;
            w0 = v ? Wr0[k] : 0.f;  w1 = v ? Wr1[k] : 0.f;
            w2 = v ? Wr2[k] : 0.f;  w3 = v ? Wr3[k] : 0.f;
        }
        #pragma unroll
        for (int kk = 0; kk < BKK; kk++) {
            float2 av = *(const float2*)&As[cur][kk][ty * 2];
            float4 wv = *(const float4*)&Ws[cur][kk][tx * 4];
            acc[0][0] += av.x * wv.x;  acc[0][1] += av.x * wv.y;
            acc[0][2] += av.x * wv.z;  acc[0][3] += av.x * wv.w;
            acc[1][0] += av.y * wv.x;  acc[1][1] += av.y * wv.y;
            acc[1][2] += av.y * wv.z;  acc[1][3] += av.y * wv.w;
        }
        if (has) {
            int nb = cur ^ 1;
            As[nb][lk][lm] = a0;  As[nb][lk][lm + 16] = a1;
            Ws[nb][lk][lm] = w0;  Ws[nb][lk][lm + 16] = w1;
            Ws[nb][lk][lm + 32] = w2;  Ws[nb][lk][lm + 48] = w3;
        }
        __syncthreads();
    }

    int n = bn + tx * 4;
    float bv0 = 0.f, bv1 = 0.f, bv2 = 0.f, bv3 = 0.f;
    if (addb) {
        bv0 = bih[n + 0] + bhh[n + 0];
        bv1 = bih[n + 1] + bhh[n + 1];
        bv2 = bih[n + 2] + bhh[n + 2];
        bv3 = bih[n + 3] + bhh[n + 3];
    }
    #pragma unroll
    for (int i = 0; i < 2; i++) {
        int m = bm + ty * 2 + i;
        float um = umask[m];
        float4 o;
        o.x = um * acc[i][0] + bv0;
        o.y = um * acc[i][1] + bv1;
        o.z = um * acc[i][2] + bv2;
        o.w = um * acc[i][3] + bv3;
        *(float4*)&out[(size_t)m * G4E + n] = o;
    }
}

// ---------------------------------------------------------------------------
// Kernel 2: LSTM recurrence (shuffle gather, double-buffered h, one barrier
// per step, prefetched xp (sums 3 chunk partials for mod0), MUFU.TANH).
// ---------------------------------------------------------------------------
__global__ void __launch_bounds__(256, 1) lstm_kernel(
    const float* __restrict__ Whh0, const float* __restrict__ Whh1) {
    int mod = blockIdx.x >> 5;
    int b = blockIdx.x & 31;
    const float* Whh = mod ? Whh1 : Whh0;
    size_t off = (size_t)b * Tt * G4E;
    const float* xpa = (mod ? g_xp1 : g_xp0a) + off;
    const float* xpb = (mod ? g_xp1 : g_xp0b) + off;
    const float* xpc = (mod ? g_xp1 : g_xp0c) + off;
    float* hout = (mod ? g_h1 : g_h0) + (size_t)b * Tt * Ee;

    int tid = threadIdx.x;
    int w = tid >> 5, l = tid & 31;
    int gt = l & 3;
    int cell = w * 8 + (l >> 2);
    int r = gt * 64 + cell;

    unsigned long long wp[32];
    {
        const float2* src = (const float2*)(Whh + (size_t)r * Ee);
        #pragma unroll
        for (int i = 0; i < 32; i++) {
            union { float2 f; unsigned long long u; } cv;
            cv.f = src[i];
            wp[i] = cv.u;
        }
    }

    __shared__ __align__(16) float hs[2][Ee];
    if (tid < Ee) hs[0][tid] = 0.f;
    float c = 0.f;
    __syncthreads();

    float gpre;
    {
        float ga = xpa[r], gb = xpb[r], gc = xpc[r];
        gpre = mod ? ga : (ga + gb + gc);
    }
    #pragma unroll 1
    for (int t = 0; t < Tt; t++) {
        float gnext = 0.f;
        if (t + 1 < Tt) {
            int idx = (t + 1) * G4E + r;
            float ga = xpa[idx], gb = xpb[idx], gc = xpc[idx];
            gnext = mod ? ga : (ga + gb + gc);
        }

        const ulonglong2* h2 = (const ulonglong2*)hs[t & 1];
        unsigned long long a0 = 0ull, a1 = 0ull, a2 = 0ull, a3 = 0ull;
        #pragma unroll
        for (int i = 0; i < 16; i += 2) {
            ulonglong2 hv = h2[i];
            a0 = ffma2(wp[2 * i + 0], hv.x, a0);
            a1 = ffma2(wp[2 * i + 1], hv.y, a1);
            ulonglong2 hv2 = h2[i + 1];
            a2 = ffma2(wp[2 * i + 2], hv2.x, a2);
            a3 = ffma2(wp[2 * i + 3], hv2.y, a3);
        }
        unsigned long long s = fadd2(fadd2(a0, a1), fadd2(a2, a3));
        float lo, hi;
        asm("mov.b64 {%0,%1}, %2;" : "=f"(lo), "=f"(hi) : "l"(s));
        float g = gpre + lo + hi;
        gpre = gnext;

        float act = (gt == 2) ? tanha(g) : fsig(g);

        float v1 = __shfl_xor_sync(0xffffffffu, act, 1);
        float v2 = __shfl_xor_sync(0xffffffffu, act, 2);
        float v3 = __shfl_xor_sync(0xffffffffu, v1, 2);

        if (gt == 0) {
            c = v1 * c + act * v2;
            float h = tanha(v3 * tanha(c));
            hs[(t + 1) & 1][cell] = h;
            hout[t * Ee + cell] = h;
        }
        __syncthreads();
    }
}

// ---------------------------------------------------------------------------
// Kernel 3: normalize + phase + measurement + MLP + log_softmax.
// 256 blocks, 8 rows each (2 groups of 4).
// ---------------------------------------------------------------------------
__global__ void __launch_bounds__(256) epilogue_kernel(
    const float* __restrict__ smask, const float* __restrict__ phase_table,
    const float* __restrict__ W1, const float* __restrict__ b1,
    const float* __restrict__ W2, const float* __restrict__ b2,
    float* __restrict__ out) {
    __shared__ float krT[Ee * Uu];
    __shared__ float kiT[Ee * Uu];
    __shared__ float W1s[CELL * 65];
    __shared__ float r0s[4][Ee], i0s[4][Ee], r1s[4][Ee], i1s[4][Ee];
    __shared__ float ms[4][2 * Uu];
    __shared__ float hids[4][CELL];
    __shared__ float preds[4][8];
    __shared__ float part[4][2][2];
    __shared__ int sidx[4];
    __shared__ float lse_s[4];

    int tid = threadIdx.x;
    int slot = tid >> 6;
    int lt = tid & 63;

    for (int i = tid; i < Ee * Uu; i += 256) { krT[i] = g_krT[i]; kiT[i] = g_kiT[i]; }
    for (int i = tid; i < CELL * CELL; i += 256) {
        int cc = i >> 6, k = i & 63;
        W1s[cc * 65 + k] = W1[i];
    }

    for (int grp = 0; grp < 2; grp++) {
        int row = blockIdx.x * 8 + grp * 4 + slot;

        float h0 = g_h0[row * Ee + lt];
        float h1 = g_h1[row * Ee + lt];
        float v0 = h0 * h0, v1 = h1 * h1;
        #pragma unroll
        for (int off = 16; off; off >>= 1) {
            v0 += __shfl_xor_sync(0xffffffffu, v0, off);
            v1 += __shfl_xor_sync(0xffffffffu, v1, off);
        }
        if ((tid & 31) == 0) { part[slot][lt >> 5][0] = v0; part[slot][lt >> 5][1] = v1; }
        if (lt == 0) {
            const float* sm = smask + row * Ss;
            float best = sm[0]; int bi = 0;
            #pragma unroll
            for (int e = 1; e < Ss; e++) { float v = sm[e]; if (v > best) { best = v; bi = e; } }
            sidx[slot] = bi;
        }
        __syncthreads();

        float s0 = part[slot][0][0] + part[slot][1][0];
        float s1 = part[slot][0][1] + part[slot][1][1];
        float inv0 = 1.f / fmaxf(sqrtf(s0), 1e-12f);
        float inv1 = 1.f / fmaxf(sqrtf(s1), 1e-12f);
        float n0 = h0 * inv0, n1 = h1 * inv1;

        float ph = phase_table[sidx[slot] * Ee + lt];
        float cp = cosf(ph), sp = sinf(ph);
        r0s[slot][lt] = cp * n0; i0s[slot][lt] = sp * n0;
        r1s[slot][lt] = cp * n1; i1s[slot][lt] = sp * n1;
        __syncthreads();

        {
            int mo = lt >> 5;
            int uu = lt & 31;
            const float* R = mo ? r1s[slot] : r0s[slot];
            const float* I = mo ? i1s[slot] : i0s[slot];
            float pr = 0.f, pi = 0.f;
            #pragma unroll 16
            for (int e = 0; e < Ee; e++) {
                float kr = krT[e * Uu + uu];
                float ki = kiT[e * Uu + uu];
                float rr = R[e], im = I[e];
                pr += kr * rr - ki * im;
                pi += ki * rr + kr * im;
            }
            ms[slot][lt] = pr * pr + pi * pi;
        }
        __syncthreads();

        {
            int cc = lt;
            float acc = b1[cc];
            #pragma unroll 16
            for (int k = 0; k < CELL; k++) acc += ms[slot][k] * W1s[cc * 65 + k];
            hids[slot][cc] = fmaxf(acc, 0.f);
        }
        __syncthreads();

        if (lt < Cc) {
            float acc = b2[lt];
            const float* w2 = W2 + lt * CELL;
            #pragma unroll 16
            for (int k = 0; k < CELL; k++) acc += hids[slot][k] * w2[k];
            preds[slot][lt] = tanhf(acc);
        }
        __syncthreads();

        if (lt == 0) {
            float m = preds[slot][0];
            #pragma unroll
            for (int k = 1; k < Cc; k++) m = fmaxf(m, preds[slot][k]);
            float se = 0.f;
            #pragma unroll
            for (int k = 0; k < Cc; k++) se += expf(preds[slot][k] - m);
            lse_s[slot] = m + logf(se);
        }
        __syncthreads();

        if (lt < Cc) out[row * Cc + lt] = preds[slot][lt] - lse_s[slot];
        __syncthreads();
    }
}

// ---------------------------------------------------------------------------
extern "C" void kernel_launch(void* const* d_in, const int* in_sizes, int n_in,
                              void* d_out, int out_size) {
    const float* x0        = (const float*)d_in[0];
    const float* x1        = (const float*)d_in[1];
    const float* smask     = (const float*)d_in[2];
    const float* umask     = (const float*)d_in[3];
    const float* W_ih0     = (const float*)d_in[4];
    const float* W_hh0     = (const float*)d_in[5];
    const float* b_ih0     = (const float*)d_in[6];
    const float* b_hh0     = (const float*)d_in[7];
    const float* W_ih1     = (const float*)d_in[8];
    const float* W_hh1     = (const float*)d_in[9];
    const float* b_ih1     = (const float*)d_in[10];
    const float* b_hh1     = (const float*)d_in[11];
    const float* phase_tab = (const float*)d_in[12];
    const float* meas_k    = (const float*)d_in[13];
    const float* W1        = (const float*)d_in[14];
    const float* b1        = (const float*)d_in[15];
    const float* W2        = (const float*)d_in[16];
    const float* b2        = (const float*)d_in[17];
    float* out = (float*)d_out;

    dim3 ggrid(5, ROWS / 32, 4);   // (5, 64, 4): 3 mod0 chunks + mod1, uniform K=100
    gemm_xproj<<<ggrid, 256>>>(x0, W_ih0, b_ih0, b_hh0,
                               x1, W_ih1, b_ih1, b_hh1, umask, meas_k);

    lstm_kernel<<<64, 256>>>(W_hh0, W_hh1);

    epilogue_kernel<<<ROWS / 8, 256>>>(smask, phase_tab, W1, b1, W2, b2, out);
}